// round 11
// baseline (speedup 1.0000x reference)
#include <cuda_runtime.h>
#include <cuda_fp16.h>
#include <math.h>
#include <stdint.h>

#define MROWS  4096   // B*S
#define DDIM   2048
#define NHEADS 16
#define HDIM   128
#define SEQ    2048
#define BATCH  2

// Scratch (static device globals; no runtime allocation)
__device__ __half g_Xhi[MROWS * DDIM];     // split input (reused per GEMM)
__device__ __half g_Xlo[MROWS * DDIM];
__device__ __half g_W16[4 * DDIM * DDIM];  // Wq,Wk,Wv,Wo in f16
__device__ __half g_Qhi[MROWS * DDIM];
__device__ __half g_Qlo[MROWS * DDIM];
__device__ __half g_K[MROWS * DDIM];
__device__ __half g_V[MROWS * DDIM];
__device__ __half g_Ahi[MROWS * DDIM];     // attention out, split
__device__ __half g_Alo[MROWS * DDIM];

// ---- helpers ----------------------------------------------------------------
__device__ __forceinline__ uint32_t smem_u32(const void* p) {
    uint32_t a;
    asm("{ .reg .u64 t; cvta.to.shared.u64 t, %1; cvt.u32.u64 %0, t; }"
        : "=r"(a) : "l"(p));
    return a;
}
__device__ __forceinline__ uint32_t sw128(uint32_t off) {
    return off ^ ((off >> 3) & 0x70);
}
__device__ __forceinline__ void cp16(uint32_t sdst, const void* gsrc) {
    asm volatile("cp.async.cg.shared.global [%0], [%1], 16;"
                 :: "r"(sdst), "l"(gsrc));
}
#define CP_COMMIT() asm volatile("cp.async.commit_group;" ::: "memory")
#define CP_WAIT(n)  asm volatile("cp.async.wait_group %0;" :: "n"(n) : "memory")

__device__ __forceinline__ void ldmx4(uint32_t* r, uint32_t addr) {
    asm volatile("ldmatrix.sync.aligned.m8n8.x4.shared.b16 {%0,%1,%2,%3}, [%4];"
                 : "=r"(r[0]), "=r"(r[1]), "=r"(r[2]), "=r"(r[3]) : "r"(addr));
}
__device__ __forceinline__ void ldmx4t(uint32_t* r, uint32_t addr) {
    asm volatile("ldmatrix.sync.aligned.m8n8.x4.trans.shared.b16 {%0,%1,%2,%3}, [%4];"
                 : "=r"(r[0]), "=r"(r[1]), "=r"(r[2]), "=r"(r[3]) : "r"(addr));
}
__device__ __forceinline__ void mma_f16(float* c, const uint32_t* a,
                                        uint32_t b0, uint32_t b1) {
    asm volatile(
        "mma.sync.aligned.m16n8k16.row.col.f32.f16.f16.f32 "
        "{%0,%1,%2,%3}, {%4,%5,%6,%7}, {%8,%9}, {%0,%1,%2,%3};"
        : "+f"(c[0]), "+f"(c[1]), "+f"(c[2]), "+f"(c[3])
        : "r"(a[0]), "r"(a[1]), "r"(a[2]), "r"(a[3]), "r"(b0), "r"(b1));
}
__device__ __forceinline__ uint32_t exp2x2(float d0, float d1) {
    uint32_t p;
    asm("{ .reg .b32 t;\n\t"
        "cvt.rn.f16x2.f32 t, %1, %2;\n\t"
        "ex2.approx.f16x2 %0, t; }"
        : "=r"(p) : "f"(d1), "f"(d0));
    return p;
}
__device__ __forceinline__ float ex2f(float x) {
    float r;
    asm("ex2.approx.ftz.f32 %0, %1;" : "=f"(r) : "f"(x));
    return r;
}

// ---------------------------------------------------------------------------
// Prep kernels (memory-bound)
// ---------------------------------------------------------------------------
__global__ __launch_bounds__(256)
void split_f32_k(const float* __restrict__ x, __half* __restrict__ hi,
                 __half* __restrict__ lo, int n4)
{
    int i = blockIdx.x * 256 + threadIdx.x;
    if (i >= n4) return;
    float4 v = ((const float4*)x)[i];
    __half2 h01 = __floats2half2_rn(v.x, v.y);
    __half2 h23 = __floats2half2_rn(v.z, v.w);
    float2 g01 = __half22float2(h01);
    float2 g23 = __half22float2(h23);
    __half2 l01 = __floats2half2_rn(v.x - g01.x, v.y - g01.y);
    __half2 l23 = __floats2half2_rn(v.z - g23.x, v.w - g23.y);
    ((uint2*)hi)[i] = make_uint2(*(uint32_t*)&h01, *(uint32_t*)&h23);
    ((uint2*)lo)[i] = make_uint2(*(uint32_t*)&l01, *(uint32_t*)&l23);
}
// one launch converts 4 weight matrices (blockIdx.y selects which)
__global__ __launch_bounds__(256)
void cvt4_f32_k(const float* __restrict__ w0, const float* __restrict__ w1,
                const float* __restrict__ w2, const float* __restrict__ w3,
                __half* __restrict__ y, int n4)
{
    int i = blockIdx.x * 256 + threadIdx.x;
    if (i >= n4) return;
    const float* src = (blockIdx.y == 0) ? w0 : (blockIdx.y == 1) ? w1
                     : (blockIdx.y == 2) ? w2 : w3;
    float4 v = ((const float4*)src)[i];
    __half2 h01 = __floats2half2_rn(v.x, v.y);
    __half2 h23 = __floats2half2_rn(v.z, v.w);
    ((uint2*)(y + (size_t)blockIdx.y * DDIM * DDIM))[i] =
        make_uint2(*(uint32_t*)&h01, *(uint32_t*)&h23);
}

// ---------------------------------------------------------------------------
// Tensor-core GEMM (NT, 2-pass split-f16, cp.async 4-stage pipeline):
//   Y = (Ahi + Alo) @ Bw^T + bias       all operands pre-converted f16
// CTA 128x128, BK=64, 512 threads (4x4 warps, 32x32 warp tile).
// ---------------------------------------------------------------------------
#define GT_TILE   (128 * 64 * 2)      // 16 KB
#define GT_STAGE  (3 * GT_TILE)       // 48 KB
#define GT_NSTAGE 4
#define GT_NCHUNK (DDIM / 64)         // 32
#define GT_SMEM   (GT_NSTAGE * GT_STAGE + 1024)

__global__ __launch_bounds__(512)
void gemm_f16_k(const __half* __restrict__ Ahi, const __half* __restrict__ Alo,
                const __half* __restrict__ Bw, const float* __restrict__ bias,
                float* __restrict__ Y, __half* __restrict__ Yhi,
                __half* __restrict__ Ylo)
{
    extern __shared__ char dsm[];
    char* smc = (char*)(((uintptr_t)dsm + 1023) & ~(uintptr_t)1023);
    const uint32_t sb = smem_u32(smc);

    const int tid  = threadIdx.x;
    const int wid  = tid >> 5;
    const int lane = tid & 31;
    const int wm = wid >> 2;
    const int wn = wid & 3;
    const int m0 = blockIdx.y * 128;
    const int n0 = blockIdx.x * 128;

    const int crow = tid >> 3;
    const int cch  = tid & 7;
    const uint32_t soff0 = sw128((uint32_t)(crow * 128 + cch * 16));
    const uint32_t soff1 = sw128((uint32_t)((crow + 64) * 128 + cch * 16));
    const __half* gA0 = Ahi + (size_t)(m0 + crow) * DDIM + cch * 8;
    const __half* gL0 = Alo + (size_t)(m0 + crow) * DDIM + cch * 8;
    const __half* gB0 = Bw  + (size_t)(n0 + crow) * DDIM + cch * 8;
    const size_t rsk = (size_t)64 * DDIM;

    float acc[2][4][4];
#pragma unroll
    for (int i = 0; i < 2; i++)
#pragma unroll
        for (int j = 0; j < 4; j++)
#pragma unroll
            for (int q = 0; q < 4; q++) acc[i][j][q] = 0.f;

    const int a_row = wm * 32 + (lane & 15);
    const int a_cb  = (lane >> 4) * 16;
    const int b_row = wn * 32 + (lane & 7) + ((lane >> 4) << 3);
    const int b_cb  = ((lane >> 3) & 1) * 16;

    // prologue: issue chunks 0..2
#pragma unroll
    for (int c = 0; c < GT_NSTAGE - 1; c++) {
        const int kh = c * 64;
        const uint32_t st = sb + c * GT_STAGE;
        cp16(st + soff0, gA0 + kh);             cp16(st + soff1, gA0 + kh + rsk);
        cp16(st + GT_TILE + soff0, gL0 + kh);   cp16(st + GT_TILE + soff1, gL0 + kh + rsk);
        cp16(st + 2*GT_TILE + soff0, gB0 + kh); cp16(st + 2*GT_TILE + soff1, gB0 + kh + rsk);
        CP_COMMIT();
    }

    for (int chunk = 0; chunk < GT_NCHUNK; chunk++) {
        if (chunk + GT_NSTAGE - 1 < GT_NCHUNK) {
            const int kh = (chunk + GT_NSTAGE - 1) * 64;
            const uint32_t st = sb + ((chunk + GT_NSTAGE - 1) & (GT_NSTAGE - 1)) * GT_STAGE;
            cp16(st + soff0, gA0 + kh);             cp16(st + soff1, gA0 + kh + rsk);
            cp16(st + GT_TILE + soff0, gL0 + kh);   cp16(st + GT_TILE + soff1, gL0 + kh + rsk);
            cp16(st + 2*GT_TILE + soff0, gB0 + kh); cp16(st + 2*GT_TILE + soff1, gB0 + kh + rsk);
            CP_COMMIT();
            CP_WAIT(3);
        } else if (chunk == GT_NCHUNK - 3) {
            CP_WAIT(2);
        } else if (chunk == GT_NCHUNK - 2) {
            CP_WAIT(1);
        } else {
            CP_WAIT(0);
        }
        __syncthreads();

        const uint32_t sAhi = sb + (chunk & (GT_NSTAGE - 1)) * GT_STAGE;
        const uint32_t sAlo = sAhi + GT_TILE;
        const uint32_t sB   = sAhi + 2 * GT_TILE;

#pragma unroll
        for (int ks = 0; ks < 4; ks++) {
            const uint32_t kb = ks * 32;
            uint32_t ah[2][4], al[2][4], bh[2][4];
#pragma unroll
            for (int mt = 0; mt < 2; mt++) {
                const uint32_t off =
                    sw128((uint32_t)((a_row + mt * 16) * 128) + kb + a_cb);
                ldmx4(ah[mt], sAhi + off);
                ldmx4(al[mt], sAlo + off);
            }
#pragma unroll
            for (int nt = 0; nt < 2; nt++) {
                const uint32_t off =
                    sw128((uint32_t)((b_row + nt * 16) * 128) + kb + b_cb);
                ldmx4(bh[nt], sB + off);
            }
#pragma unroll
            for (int mt = 0; mt < 2; mt++)
#pragma unroll
                for (int nt = 0; nt < 2; nt++)
#pragma unroll
                    for (int h = 0; h < 2; h++) {
                        float* c = acc[mt][nt * 2 + h];
                        mma_f16(c, ah[mt], bh[nt][2 * h], bh[nt][2 * h + 1]);
                        mma_f16(c, al[mt], bh[nt][2 * h], bh[nt][2 * h + 1]);
                    }
        }
        __syncthreads();
    }

    const int g  = lane >> 2;
    const int tg = lane & 3;
#pragma unroll
    for (int mt = 0; mt < 2; mt++) {
        const int row = m0 + wm * 32 + mt * 16 + g;
#pragma unroll
        for (int nt8 = 0; nt8 < 4; nt8++) {
            const int col = n0 + wn * 32 + nt8 * 8 + tg * 2;
            const float b0 = bias[col], b1 = bias[col + 1];
            float v00 = acc[mt][nt8][0] + b0, v01 = acc[mt][nt8][1] + b1;
            float v10 = acc[mt][nt8][2] + b0, v11 = acc[mt][nt8][3] + b1;
            if (Y) {
                float* y0 = Y + (size_t)row * DDIM + col;
                float* y1 = Y + (size_t)(row + 8) * DDIM + col;
                y0[0] = v00; y0[1] = v01;
                y1[0] = v10; y1[1] = v11;
            } else if (Ylo) {
                __half h00 = __float2half_rn(v00), h01 = __float2half_rn(v01);
                __half h10 = __float2half_rn(v10), h11 = __float2half_rn(v11);
                __half l00 = __float2half_rn(v00 - __half2float(h00));
                __half l01 = __float2half_rn(v01 - __half2float(h01));
                __half l10 = __float2half_rn(v10 - __half2float(h10));
                __half l11 = __float2half_rn(v11 - __half2float(h11));
                *(__half2*)(Yhi + (size_t)row * DDIM + col)       = __halves2half2(h00, h01);
                *(__half2*)(Ylo + (size_t)row * DDIM + col)       = __halves2half2(l00, l01);
                *(__half2*)(Yhi + (size_t)(row + 8) * DDIM + col) = __halves2half2(h10, h11);
                *(__half2*)(Ylo + (size_t)(row + 8) * DDIM + col) = __halves2half2(l10, l11);
            } else {
                *(__half2*)(Yhi + (size_t)row * DDIM + col) =
                    __floats2half2_rn(v00, v01);
                *(__half2*)(Yhi + (size_t)(row + 8) * DDIM + col) =
                    __floats2half2_rn(v10, v11);
            }
        }
    }
}

// ---------------------------------------------------------------------------
// Flash attention, tensor-core, cp.async double-buffered K/V.
// Q split hi/lo (2-pass QK), K/V single f16 (1-pass AV).
// BM=128/CTA, 8 warps x 16 rows, BN=128, Hd=128. smem 192KB.
// Output: f16 hi/lo split (consumed by the O-projection GEMM).
// ---------------------------------------------------------------------------
#define FKS 0.12751744f   // (1/sqrt(128)) * log2(e)
#define FA_SMEM (6 * 32768)

__device__ __forceinline__ uint32_t off16(uint32_t row, uint32_t cb) {
    return ((cb >> 7) << 14) + sw128((row << 7) + (cb & 127));
}

__global__ __launch_bounds__(256)
void flash_mma_k(const __half* __restrict__ Qhi, const __half* __restrict__ Qlo,
                 const __half* __restrict__ Kp, const __half* __restrict__ Vp,
                 __half* __restrict__ Ohi, __half* __restrict__ Olo)
{
    extern __shared__ char fsm[];
    char* cQh = fsm;
    char* cQl = fsm + 32768;
    const uint32_t sQh = smem_u32(fsm);
    const uint32_t sQl = sQh + 32768;
    const uint32_t sStage0 = sQh + 65536;     // [K0|V0], [K1|V1] each 64KB

    const int tid  = threadIdx.x;
    const int wid  = tid >> 5;
    const int lane = tid & 31;
    const int qt = blockIdx.x, h = blockIdx.y, b = blockIdx.z;
    const int wr = wid << 4;
    const int hc = h * HDIM;
    const size_t rowbase = (size_t)b * SEQ;

    // Q tile (plain loads, once)
    for (int i = tid; i < 2048; i += 256) {
        const uint32_t row = i >> 4;
        const uint32_t cb  = (i & 15) * 16;
        const size_t g = (rowbase + qt * 128 + row) * DDIM + hc + (cb >> 1);
        const uint32_t off = off16(row, cb);
        *(uint4*)(cQh + off) = *(const uint4*)(Qhi + g);
        *(uint4*)(cQl + off) = *(const uint4*)(Qlo + g);
    }

    // per-thread K/V cp.async mapping (8 rows x 1 chunk each)
    const uint32_t lrow = tid >> 4;
    const uint32_t lcb  = (tid & 15) * 16;
    const uint32_t loff[8] = {
        off16(lrow, lcb),       off16(lrow + 16, lcb),
        off16(lrow + 32, lcb),  off16(lrow + 48, lcb),
        off16(lrow + 64, lcb),  off16(lrow + 80, lcb),
        off16(lrow + 96, lcb),  off16(lrow + 112, lcb)
    };

    {
        const uint32_t st = sStage0;
#pragma unroll
        for (int t = 0; t < 8; t++) {
            const size_t g = (rowbase + lrow + 16 * t) * DDIM + hc + (lcb >> 1);
            cp16(st + loff[t], Kp + g);
            cp16(st + 32768 + loff[t], Vp + g);
        }
        CP_COMMIT();
    }

    float o[17][4];
#pragma unroll
    for (int t = 0; t < 17; t++)
#pragma unroll
        for (int q = 0; q < 4; q++) o[t][q] = 0.f;
    float m_lo = -1e30f, m_hi = -1e30f;

    const uint32_t b_ones = (lane < 4) ? 0x3C003C00u : 0u;

    for (int jt = 0; jt < SEQ / 128; jt++) {
        if (jt + 1 < SEQ / 128) {
            const uint32_t st = sStage0 + ((jt + 1) & 1) * 65536;
#pragma unroll
            for (int t = 0; t < 8; t++) {
                const size_t g = (rowbase + (jt + 1) * 128 + lrow + 16 * t) * DDIM
                               + hc + (lcb >> 1);
                cp16(st + loff[t], Kp + g);
                cp16(st + 32768 + loff[t], Vp + g);
            }
            CP_COMMIT();
            CP_WAIT(1);
        } else {
            CP_WAIT(0);
        }
        __syncthreads();

        const uint32_t sK = sStage0 + (jt & 1) * 65536;
        const uint32_t sV = sK + 32768;

        // ---- scores S = Q.K^T (2-pass) ----
        float s[16][4];
#pragma unroll
        for (int t = 0; t < 16; t++)
#pragma unroll
            for (int q = 0; q < 4; q++) s[t][q] = 0.f;

#pragma unroll
        for (int ks = 0; ks < 8; ks++) {
            const uint32_t kb = ks * 32;
            uint32_t ah[4], al[4];
            const uint32_t aoff = off16(wr + (lane & 15), kb + ((lane >> 4) << 4));
            ldmx4(ah, sQh + aoff);
            ldmx4(al, sQl + aoff);
#pragma unroll
            for (int ntp = 0; ntp < 8; ntp++) {
                uint32_t bh[4];
                const uint32_t nr  = ntp * 16 + (lane & 7) + ((lane >> 4) << 3);
                const uint32_t boff = off16(nr, kb + (((lane >> 3) & 1) << 4));
                ldmx4(bh, sK + boff);
#pragma unroll
                for (int hh = 0; hh < 2; hh++) {
                    float* c = s[ntp * 2 + hh];
                    mma_f16(c, ah, bh[2 * hh], bh[2 * hh + 1]);
                    mma_f16(c, al, bh[2 * hh], bh[2 * hh + 1]);
                }
            }
        }

        // ---- online softmax ----
        float mloc_lo = -1e30f, mloc_hi = -1e30f;
#pragma unroll
        for (int t = 0; t < 16; t++) {
            mloc_lo = fmaxf(mloc_lo, fmaxf(s[t][0], s[t][1]));
            mloc_hi = fmaxf(mloc_hi, fmaxf(s[t][2], s[t][3]));
        }
        mloc_lo = fmaxf(mloc_lo, __shfl_xor_sync(0xffffffffu, mloc_lo, 1));
        mloc_lo = fmaxf(mloc_lo, __shfl_xor_sync(0xffffffffu, mloc_lo, 2));
        mloc_hi = fmaxf(mloc_hi, __shfl_xor_sync(0xffffffffu, mloc_hi, 1));
        mloc_hi = fmaxf(mloc_hi, __shfl_xor_sync(0xffffffffu, mloc_hi, 2));

        const float mn_lo = fmaxf(m_lo, mloc_lo);
        const float mn_hi = fmaxf(m_hi, mloc_hi);
        const float al_lo = ex2f((m_lo - mn_lo) * FKS);
        const float al_hi = ex2f((m_hi - mn_hi) * FKS);
        m_lo = mn_lo; m_hi = mn_hi;
        const float mk_lo = mn_lo * FKS;
        const float mk_hi = mn_hi * FKS;

        uint32_t pex[16][2];
#pragma unroll
        for (int t = 0; t < 16; t++) {
            pex[t][0] = exp2x2(fmaf(s[t][0], FKS, -mk_lo), fmaf(s[t][1], FKS, -mk_lo));
            pex[t][1] = exp2x2(fmaf(s[t][2], FKS, -mk_hi), fmaf(s[t][3], FKS, -mk_hi));
        }
#pragma unroll
        for (int t = 0; t < 17; t++) {
            o[t][0] *= al_lo; o[t][1] *= al_lo;
            o[t][2] *= al_hi; o[t][3] *= al_hi;
        }

        // ---- AV + l (ones column) ----
#pragma unroll
        for (int ks = 0; ks < 8; ks++) {
            uint32_t a[4] = { pex[2 * ks][0], pex[2 * ks][1],
                              pex[2 * ks + 1][0], pex[2 * ks + 1][1] };
            const uint32_t vr = ks * 16 + (lane & 15);
#pragma unroll
            for (int dp = 0; dp < 8; dp++) {
                uint32_t vh[4];
                const uint32_t voff = off16(vr, dp * 32 + ((lane >> 4) << 4));
                ldmx4t(vh, sV + voff);
                mma_f16(o[2 * dp],     a, vh[0], vh[1]);
                mma_f16(o[2 * dp + 1], a, vh[2], vh[3]);
            }
            mma_f16(o[16], a, b_ones, b_ones);
        }
        __syncthreads();
    }

    // epilogue: divide by l, split to f16 hi/lo
    const float l_lo = __shfl_sync(0xffffffffu, o[16][0], lane & 28);
    const float l_hi = __shfl_sync(0xffffffffu, o[16][2], lane & 28);
    const float inv_lo = 1.f / l_lo;
    const float inv_hi = 1.f / l_hi;
    const size_t rg = rowbase + qt * 128 + wr + (lane >> 2);
    const int cb2 = hc + 2 * (lane & 3);
#pragma unroll
    for (int t = 0; t < 16; t++) {
        float2 v0 = make_float2(o[t][0] * inv_lo, o[t][1] * inv_lo);
        float2 v1 = make_float2(o[t][2] * inv_hi, o[t][3] * inv_hi);
        __half2 h0 = __floats2half2_rn(v0.x, v0.y);
        __half2 h1 = __floats2half2_rn(v1.x, v1.y);
        float2 f0 = __half22float2(h0);
        float2 f1 = __half22float2(h1);
        __half2 l0 = __floats2half2_rn(v0.x - f0.x, v0.y - f0.y);
        __half2 l1 = __floats2half2_rn(v1.x - f1.x, v1.y - f1.y);
        *(__half2*)(Ohi + rg * DDIM + cb2 + 8 * t)       = h0;
        *(__half2*)(Olo + rg * DDIM + cb2 + 8 * t)       = l0;
        *(__half2*)(Ohi + (rg + 8) * DDIM + cb2 + 8 * t) = h1;
        *(__half2*)(Olo + (rg + 8) * DDIM + cb2 + 8 * t) = l1;
    }
}

// ---------------------------------------------------------------------------
extern "C" void kernel_launch(void* const* d_in, const int* in_sizes, int n_in,
                              void* d_out, int out_size)
{
    (void)in_sizes; (void)n_in; (void)out_size;
    const float* query  = (const float*)d_in[0];
    const float* key_in = (const float*)d_in[1];
    const float* value  = (const float*)d_in[2];
    const float* Wq = (const float*)d_in[3];
    const float* bq = (const float*)d_in[4];
    const float* Wk = (const float*)d_in[5];
    const float* bk = (const float*)d_in[6];
    const float* Wv = (const float*)d_in[7];
    const float* bv = (const float*)d_in[8];
    const float* Wo = (const float*)d_in[9];
    const float* bo = (const float*)d_in[10];
    float* out = (float*)d_out;

    __half *pXh, *pXl, *pW, *pQh, *pQl, *pK, *pV, *pAh, *pAl;
    cudaGetSymbolAddress((void**)&pXh, g_Xhi);
    cudaGetSymbolAddress((void**)&pXl, g_Xlo);
    cudaGetSymbolAddress((void**)&pW,  g_W16);
    cudaGetSymbolAddress((void**)&pQh, g_Qhi);
    cudaGetSymbolAddress((void**)&pQl, g_Qlo);
    cudaGetSymbolAddress((void**)&pK,  g_K);
    cudaGetSymbolAddress((void**)&pV,  g_V);
    cudaGetSymbolAddress((void**)&pAh, g_Ahi);
    cudaGetSymbolAddress((void**)&pAl, g_Alo);

    cudaFuncSetAttribute(gemm_f16_k,
                         cudaFuncAttributeMaxDynamicSharedMemorySize, GT_SMEM);
    cudaFuncSetAttribute(flash_mma_k,
                         cudaFuncAttributeMaxDynamicSharedMemorySize, FA_SMEM);

    const int nW4 = DDIM * DDIM / 4;
    const int nX4 = MROWS * DDIM / 4;
    const int gW = (nW4 + 255) / 256;
    const int gX = (nX4 + 255) / 256;
    __half* pWq = pW;
    __half* pWk = pW + (size_t)DDIM * DDIM;
    __half* pWv = pW + 2 * (size_t)DDIM * DDIM;
    __half* pWo = pW + 3 * (size_t)DDIM * DDIM;

    cvt4_f32_k<<<dim3(gW, 4), 256>>>(Wq, Wk, Wv, Wo, pW, nW4);

    dim3 gg(DDIM / 128, MROWS / 128);

    split_f32_k<<<gX, 256>>>(query, pXh, pXl, nX4);
    gemm_f16_k<<<gg, 512, GT_SMEM>>>(pXh, pXl, pWq, bq, nullptr, pQh, pQl);
    split_f32_k<<<gX, 256>>>(key_in, pXh, pXl, nX4);
    gemm_f16_k<<<gg, 512, GT_SMEM>>>(pXh, pXl, pWk, bk, nullptr, pK, nullptr);
    split_f32_k<<<gX, 256>>>(value, pXh, pXl, nX4);
    gemm_f16_k<<<gg, 512, GT_SMEM>>>(pXh, pXl, pWv, bv, nullptr, pV, nullptr);

    flash_mma_k<<<dim3(SEQ / 128, NHEADS, BATCH), 256, FA_SMEM>>>(
        pQh, pQl, pK, pV, pAh, pAl);

    gemm_f16_k<<<gg, 512, GT_SMEM>>>(pAh, pAl, pWo, bo, out, nullptr, nullptr);
}

// round 12
// speedup vs baseline: 1.3999x; 1.3999x over previous
#include <cuda_runtime.h>
#include <cuda_fp16.h>
#include <math.h>
#include <stdint.h>

#define MROWS  4096   // B*S
#define DDIM   2048
#define NHEADS 16
#define HDIM   128
#define SEQ    2048
#define BATCH  2

// Scratch (static device globals; no runtime allocation)
__device__ __half g_Xin[3 * MROWS * DDIM]; // query/key/value in f16
__device__ __half g_W16[4 * DDIM * DDIM];  // Wq,Wk,Wv,Wo in f16
__device__ __half g_Q[MROWS * DDIM];
__device__ __half g_K[MROWS * DDIM];
__device__ __half g_V[MROWS * DDIM];
__device__ __half g_Ahi[MROWS * DDIM];     // attention out, split
__device__ __half g_Alo[MROWS * DDIM];

// ---- helpers ----------------------------------------------------------------
__device__ __forceinline__ uint32_t smem_u32(const void* p) {
    uint32_t a;
    asm("{ .reg .u64 t; cvta.to.shared.u64 t, %1; cvt.u32.u64 %0, t; }"
        : "=r"(a) : "l"(p));
    return a;
}
__device__ __forceinline__ uint32_t sw128(uint32_t off) {
    return off ^ ((off >> 3) & 0x70);
}
__device__ __forceinline__ void cp16(uint32_t sdst, const void* gsrc) {
    asm volatile("cp.async.cg.shared.global [%0], [%1], 16;"
                 :: "r"(sdst), "l"(gsrc));
}
#define CP_COMMIT() asm volatile("cp.async.commit_group;" ::: "memory")
#define CP_WAIT(n)  asm volatile("cp.async.wait_group %0;" :: "n"(n) : "memory")

__device__ __forceinline__ void ldmx4(uint32_t* r, uint32_t addr) {
    asm volatile("ldmatrix.sync.aligned.m8n8.x4.shared.b16 {%0,%1,%2,%3}, [%4];"
                 : "=r"(r[0]), "=r"(r[1]), "=r"(r[2]), "=r"(r[3]) : "r"(addr));
}
__device__ __forceinline__ void ldmx4t(uint32_t* r, uint32_t addr) {
    asm volatile("ldmatrix.sync.aligned.m8n8.x4.trans.shared.b16 {%0,%1,%2,%3}, [%4];"
                 : "=r"(r[0]), "=r"(r[1]), "=r"(r[2]), "=r"(r[3]) : "r"(addr));
}
__device__ __forceinline__ void mma_f16(float* c, const uint32_t* a,
                                        uint32_t b0, uint32_t b1) {
    asm volatile(
        "mma.sync.aligned.m16n8k16.row.col.f32.f16.f16.f32 "
        "{%0,%1,%2,%3}, {%4,%5,%6,%7}, {%8,%9}, {%0,%1,%2,%3};"
        : "+f"(c[0]), "+f"(c[1]), "+f"(c[2]), "+f"(c[3])
        : "r"(a[0]), "r"(a[1]), "r"(a[2]), "r"(a[3]), "r"(b0), "r"(b1));
}
__device__ __forceinline__ uint32_t exp2x2(float d0, float d1) {
    uint32_t p;
    asm("{ .reg .b32 t;\n\t"
        "cvt.rn.f16x2.f32 t, %1, %2;\n\t"
        "ex2.approx.f16x2 %0, t; }"
        : "=r"(p) : "f"(d1), "f"(d0));
    return p;
}
__device__ __forceinline__ float ex2f(float x) {
    float r;
    asm("ex2.approx.ftz.f32 %0, %1;" : "=f"(r) : "f"(x));
    return r;
}

// ---------------------------------------------------------------------------
// Prep kernels (memory-bound)
// ---------------------------------------------------------------------------
// one launch converts 3 inputs (blockIdx.y selects which)
__global__ __launch_bounds__(256)
void cvt3_f32_k(const float* __restrict__ x0, const float* __restrict__ x1,
                const float* __restrict__ x2, __half* __restrict__ y, int n4)
{
    int i = blockIdx.x * 256 + threadIdx.x;
    if (i >= n4) return;
    const float* src = (blockIdx.y == 0) ? x0 : (blockIdx.y == 1) ? x1 : x2;
    float4 v = ((const float4*)src)[i];
    __half2 h01 = __floats2half2_rn(v.x, v.y);
    __half2 h23 = __floats2half2_rn(v.z, v.w);
    ((uint2*)(y + (size_t)blockIdx.y * MROWS * DDIM))[i] =
        make_uint2(*(uint32_t*)&h01, *(uint32_t*)&h23);
}
// one launch converts 4 weight matrices (blockIdx.y selects which)
__global__ __launch_bounds__(256)
void cvt4_f32_k(const float* __restrict__ w0, const float* __restrict__ w1,
                const float* __restrict__ w2, const float* __restrict__ w3,
                __half* __restrict__ y, int n4)
{
    int i = blockIdx.x * 256 + threadIdx.x;
    if (i >= n4) return;
    const float* src = (blockIdx.y == 0) ? w0 : (blockIdx.y == 1) ? w1
                     : (blockIdx.y == 2) ? w2 : w3;
    float4 v = ((const float4*)src)[i];
    __half2 h01 = __floats2half2_rn(v.x, v.y);
    __half2 h23 = __floats2half2_rn(v.z, v.w);
    ((uint2*)(y + (size_t)blockIdx.y * DDIM * DDIM))[i] =
        make_uint2(*(uint32_t*)&h01, *(uint32_t*)&h23);
}

// ---------------------------------------------------------------------------
// Tensor-core GEMM (NT, f16, cp.async 2-stage pipeline):
//   TP=true : Y = (Ahi + Alo) @ Bw^T + bias   (2-pass split-f16 A)
//   TP=false: Y = A @ Bw^T + bias             (1-pass, A single f16)
// CTA 128x128, BK=64, 512 threads (4x4 warps, 32x32 warp tile).
// Output: Y (fp32) | Yhi+Ylo (split f16) | Yhi (single f16).
// ---------------------------------------------------------------------------
#define GT_TILE   (128 * 64 * 2)      // 16 KB
#define GT_NCHUNK (DDIM / 64)         // 32
#define GT_SMEM2P (2 * 3 * GT_TILE + 1024)
#define GT_SMEM1P (2 * 2 * GT_TILE + 1024)

template<bool TP>
__global__ __launch_bounds__(512)
void gemm_f16_k(const __half* __restrict__ Ahi, const __half* __restrict__ Alo,
                const __half* __restrict__ Bw, const float* __restrict__ bias,
                float* __restrict__ Y, __half* __restrict__ Yhi,
                __half* __restrict__ Ylo)
{
    constexpr uint32_t STAGE = (TP ? 3 : 2) * GT_TILE;
    constexpr uint32_t BOFF  = (TP ? 2 : 1) * GT_TILE;

    extern __shared__ char dsm[];
    char* smc = (char*)(((uintptr_t)dsm + 1023) & ~(uintptr_t)1023);
    const uint32_t sb = smem_u32(smc);

    const int tid  = threadIdx.x;
    const int wid  = tid >> 5;
    const int lane = tid & 31;
    const int wm = wid >> 2;
    const int wn = wid & 3;
    const int m0 = blockIdx.y * 128;
    const int n0 = blockIdx.x * 128;

    const int crow = tid >> 3;
    const int cch  = tid & 7;
    const uint32_t soff0 = sw128((uint32_t)(crow * 128 + cch * 16));
    const uint32_t soff1 = sw128((uint32_t)((crow + 64) * 128 + cch * 16));
    const __half* gA0 = Ahi + (size_t)(m0 + crow) * DDIM + cch * 8;
    const __half* gL0 = TP ? (Alo + (size_t)(m0 + crow) * DDIM + cch * 8) : nullptr;
    const __half* gB0 = Bw  + (size_t)(n0 + crow) * DDIM + cch * 8;
    const size_t rsk = (size_t)64 * DDIM;

    float acc[2][4][4];
#pragma unroll
    for (int i = 0; i < 2; i++)
#pragma unroll
        for (int j = 0; j < 4; j++)
#pragma unroll
            for (int q = 0; q < 4; q++) acc[i][j][q] = 0.f;

    const int a_row = wm * 32 + (lane & 15);
    const int a_cb  = (lane >> 4) * 16;
    const int b_row = wn * 32 + (lane & 7) + ((lane >> 4) << 3);
    const int b_cb  = ((lane >> 3) & 1) * 16;

    // prologue: issue chunk 0
    {
        const uint32_t st = sb;
        cp16(st + soff0, gA0);              cp16(st + soff1, gA0 + rsk);
        if (TP) { cp16(st + GT_TILE + soff0, gL0); cp16(st + GT_TILE + soff1, gL0 + rsk); }
        cp16(st + BOFF + soff0, gB0);       cp16(st + BOFF + soff1, gB0 + rsk);
        CP_COMMIT();
    }

    for (int chunk = 0; chunk < GT_NCHUNK; chunk++) {
        if (chunk + 1 < GT_NCHUNK) {
            const int kh = (chunk + 1) * 64;
            const uint32_t st = sb + ((chunk + 1) & 1) * STAGE;
            cp16(st + soff0, gA0 + kh);              cp16(st + soff1, gA0 + kh + rsk);
            if (TP) { cp16(st + GT_TILE + soff0, gL0 + kh); cp16(st + GT_TILE + soff1, gL0 + kh + rsk); }
            cp16(st + BOFF + soff0, gB0 + kh);       cp16(st + BOFF + soff1, gB0 + kh + rsk);
            CP_COMMIT();
            CP_WAIT(1);
        } else {
            CP_WAIT(0);
        }
        __syncthreads();

        const uint32_t sA = sb + (chunk & 1) * STAGE;
        const uint32_t sL = sA + GT_TILE;
        const uint32_t sB = sA + BOFF;

#pragma unroll
        for (int ks = 0; ks < 4; ks++) {
            const uint32_t kb = ks * 32;
            uint32_t ah[2][4], al[2][4], bh[2][4];
#pragma unroll
            for (int mt = 0; mt < 2; mt++) {
                const uint32_t off =
                    sw128((uint32_t)((a_row + mt * 16) * 128) + kb + a_cb);
                ldmx4(ah[mt], sA + off);
                if (TP) ldmx4(al[mt], sL + off);
            }
#pragma unroll
            for (int nt = 0; nt < 2; nt++) {
                const uint32_t off =
                    sw128((uint32_t)((b_row + nt * 16) * 128) + kb + b_cb);
                ldmx4(bh[nt], sB + off);
            }
#pragma unroll
            for (int mt = 0; mt < 2; mt++)
#pragma unroll
                for (int nt = 0; nt < 2; nt++)
#pragma unroll
                    for (int h = 0; h < 2; h++) {
                        float* c = acc[mt][nt * 2 + h];
                        mma_f16(c, ah[mt], bh[nt][2 * h], bh[nt][2 * h + 1]);
                        if (TP) mma_f16(c, al[mt], bh[nt][2 * h], bh[nt][2 * h + 1]);
                    }
        }
        __syncthreads();
    }

    const int g  = lane >> 2;
    const int tg = lane & 3;
#pragma unroll
    for (int mt = 0; mt < 2; mt++) {
        const int row = m0 + wm * 32 + mt * 16 + g;
#pragma unroll
        for (int nt8 = 0; nt8 < 4; nt8++) {
            const int col = n0 + wn * 32 + nt8 * 8 + tg * 2;
            const float b0 = bias[col], b1 = bias[col + 1];
            float v00 = acc[mt][nt8][0] + b0, v01 = acc[mt][nt8][1] + b1;
            float v10 = acc[mt][nt8][2] + b0, v11 = acc[mt][nt8][3] + b1;
            if (Y) {
                float* y0 = Y + (size_t)row * DDIM + col;
                float* y1 = Y + (size_t)(row + 8) * DDIM + col;
                y0[0] = v00; y0[1] = v01;
                y1[0] = v10; y1[1] = v11;
            } else if (Ylo) {
                __half h00 = __float2half_rn(v00), h01 = __float2half_rn(v01);
                __half h10 = __float2half_rn(v10), h11 = __float2half_rn(v11);
                __half l00 = __float2half_rn(v00 - __half2float(h00));
                __half l01 = __float2half_rn(v01 - __half2float(h01));
                __half l10 = __float2half_rn(v10 - __half2float(h10));
                __half l11 = __float2half_rn(v11 - __half2float(h11));
                *(__half2*)(Yhi + (size_t)row * DDIM + col)       = __halves2half2(h00, h01);
                *(__half2*)(Ylo + (size_t)row * DDIM + col)       = __halves2half2(l00, l01);
                *(__half2*)(Yhi + (size_t)(row + 8) * DDIM + col) = __halves2half2(h10, h11);
                *(__half2*)(Ylo + (size_t)(row + 8) * DDIM + col) = __halves2half2(l10, l11);
            } else {
                *(__half2*)(Yhi + (size_t)row * DDIM + col) =
                    __floats2half2_rn(v00, v01);
                *(__half2*)(Yhi + (size_t)(row + 8) * DDIM + col) =
                    __floats2half2_rn(v10, v11);
            }
        }
    }
}

// ---------------------------------------------------------------------------
// Flash attention, tensor-core, cp.async double-buffered K/V.
// Q/K/V single f16 (1-pass QK, 1-pass AV).
// BM=128/CTA, 8 warps x 16 rows, BN=128, Hd=128. smem 160KB.
// Output: f16 hi/lo split (consumed by the O-projection GEMM).
// ---------------------------------------------------------------------------
#define FKS 0.12751744f   // (1/sqrt(128)) * log2(e)
#define FA_SMEM (5 * 32768)

__device__ __forceinline__ uint32_t off16(uint32_t row, uint32_t cb) {
    return ((cb >> 7) << 14) + sw128((row << 7) + (cb & 127));
}

__global__ __launch_bounds__(256)
void flash_mma_k(const __half* __restrict__ Qp,
                 const __half* __restrict__ Kp, const __half* __restrict__ Vp,
                 __half* __restrict__ Ohi, __half* __restrict__ Olo)
{
    extern __shared__ char fsm[];
    char* cQ = fsm;
    const uint32_t sQ = smem_u32(fsm);
    const uint32_t sStage0 = sQ + 32768;      // [K0|V0], [K1|V1] each 64KB

    const int tid  = threadIdx.x;
    const int wid  = tid >> 5;
    const int lane = tid & 31;
    const int qt = blockIdx.x, h = blockIdx.y, b = blockIdx.z;
    const int wr = wid << 4;
    const int hc = h * HDIM;
    const size_t rowbase = (size_t)b * SEQ;

    // Q tile (plain loads, once)
    for (int i = tid; i < 2048; i += 256) {
        const uint32_t row = i >> 4;
        const uint32_t cb  = (i & 15) * 16;
        const size_t g = (rowbase + qt * 128 + row) * DDIM + hc + (cb >> 1);
        *(uint4*)(cQ + off16(row, cb)) = *(const uint4*)(Qp + g);
    }

    // per-thread K/V cp.async mapping (8 rows x 1 chunk each)
    const uint32_t lrow = tid >> 4;
    const uint32_t lcb  = (tid & 15) * 16;
    const uint32_t loff[8] = {
        off16(lrow, lcb),       off16(lrow + 16, lcb),
        off16(lrow + 32, lcb),  off16(lrow + 48, lcb),
        off16(lrow + 64, lcb),  off16(lrow + 80, lcb),
        off16(lrow + 96, lcb),  off16(lrow + 112, lcb)
    };

    {
        const uint32_t st = sStage0;
#pragma unroll
        for (int t = 0; t < 8; t++) {
            const size_t g = (rowbase + lrow + 16 * t) * DDIM + hc + (lcb >> 1);
            cp16(st + loff[t], Kp + g);
            cp16(st + 32768 + loff[t], Vp + g);
        }
        CP_COMMIT();
    }

    float o[17][4];
#pragma unroll
    for (int t = 0; t < 17; t++)
#pragma unroll
        for (int q = 0; q < 4; q++) o[t][q] = 0.f;
    float m_lo = -1e30f, m_hi = -1e30f;

    const uint32_t b_ones = (lane < 4) ? 0x3C003C00u : 0u;

    for (int jt = 0; jt < SEQ / 128; jt++) {
        if (jt + 1 < SEQ / 128) {
            const uint32_t st = sStage0 + ((jt + 1) & 1) * 65536;
#pragma unroll
            for (int t = 0; t < 8; t++) {
                const size_t g = (rowbase + (jt + 1) * 128 + lrow + 16 * t) * DDIM
                               + hc + (lcb >> 1);
                cp16(st + loff[t], Kp + g);
                cp16(st + 32768 + loff[t], Vp + g);
            }
            CP_COMMIT();
            CP_WAIT(1);
        } else {
            CP_WAIT(0);
        }
        __syncthreads();

        const uint32_t sK = sStage0 + (jt & 1) * 65536;
        const uint32_t sV = sK + 32768;

        // ---- scores S = Q.K^T (1-pass) ----
        float s[16][4];
#pragma unroll
        for (int t = 0; t < 16; t++)
#pragma unroll
            for (int q = 0; q < 4; q++) s[t][q] = 0.f;

#pragma unroll
        for (int ks = 0; ks < 8; ks++) {
            const uint32_t kb = ks * 32;
            uint32_t ah[4];
            const uint32_t aoff = off16(wr + (lane & 15), kb + ((lane >> 4) << 4));
            ldmx4(ah, sQ + aoff);
#pragma unroll
            for (int ntp = 0; ntp < 8; ntp++) {
                uint32_t bh[4];
                const uint32_t nr  = ntp * 16 + (lane & 7) + ((lane >> 4) << 3);
                const uint32_t boff = off16(nr, kb + (((lane >> 3) & 1) << 4));
                ldmx4(bh, sK + boff);
#pragma unroll
                for (int hh = 0; hh < 2; hh++) {
                    float* c = s[ntp * 2 + hh];
                    mma_f16(c, ah, bh[2 * hh], bh[2 * hh + 1]);
                }
            }
        }

        // ---- online softmax ----
        float mloc_lo = -1e30f, mloc_hi = -1e30f;
#pragma unroll
        for (int t = 0; t < 16; t++) {
            mloc_lo = fmaxf(mloc_lo, fmaxf(s[t][0], s[t][1]));
            mloc_hi = fmaxf(mloc_hi, fmaxf(s[t][2], s[t][3]));
        }
        mloc_lo = fmaxf(mloc_lo, __shfl_xor_sync(0xffffffffu, mloc_lo, 1));
        mloc_lo = fmaxf(mloc_lo, __shfl_xor_sync(0xffffffffu, mloc_lo, 2));
        mloc_hi = fmaxf(mloc_hi, __shfl_xor_sync(0xffffffffu, mloc_hi, 1));
        mloc_hi = fmaxf(mloc_hi, __shfl_xor_sync(0xffffffffu, mloc_hi, 2));

        const float mn_lo = fmaxf(m_lo, mloc_lo);
        const float mn_hi = fmaxf(m_hi, mloc_hi);
        const float al_lo = ex2f((m_lo - mn_lo) * FKS);
        const float al_hi = ex2f((m_hi - mn_hi) * FKS);
        m_lo = mn_lo; m_hi = mn_hi;
        const float mk_lo = mn_lo * FKS;
        const float mk_hi = mn_hi * FKS;

        uint32_t pex[16][2];
#pragma unroll
        for (int t = 0; t < 16; t++) {
            pex[t][0] = exp2x2(fmaf(s[t][0], FKS, -mk_lo), fmaf(s[t][1], FKS, -mk_lo));
            pex[t][1] = exp2x2(fmaf(s[t][2], FKS, -mk_hi), fmaf(s[t][3], FKS, -mk_hi));
        }
#pragma unroll
        for (int t = 0; t < 17; t++) {
            o[t][0] *= al_lo; o[t][1] *= al_lo;
            o[t][2] *= al_hi; o[t][3] *= al_hi;
        }

        // ---- AV + l (ones column) ----
#pragma unroll
        for (int ks = 0; ks < 8; ks++) {
            uint32_t a[4] = { pex[2 * ks][0], pex[2 * ks][1],
                              pex[2 * ks + 1][0], pex[2 * ks + 1][1] };
            const uint32_t vr = ks * 16 + (lane & 15);
#pragma unroll
            for (int dp = 0; dp < 8; dp++) {
                uint32_t vh[4];
                const uint32_t voff = off16(vr, dp * 32 + ((lane >> 4) << 4));
                ldmx4t(vh, sV + voff);
                mma_f16(o[2 * dp],     a, vh[0], vh[1]);
                mma_f16(o[2 * dp + 1], a, vh[2], vh[3]);
            }
            mma_f16(o[16], a, b_ones, b_ones);
        }
        __syncthreads();
    }

    // epilogue: divide by l, split to f16 hi/lo
    const float l_lo = __shfl_sync(0xffffffffu, o[16][0], lane & 28);
    const float l_hi = __shfl_sync(0xffffffffu, o[16][2], lane & 28);
    const float inv_lo = 1.f / l_lo;
    const float inv_hi = 1.f / l_hi;
    const size_t rg = rowbase + qt * 128 + wr + (lane >> 2);
    const int cb2 = hc + 2 * (lane & 3);
#pragma unroll
    for (int t = 0; t < 16; t++) {
        float2 v0 = make_float2(o[t][0] * inv_lo, o[t][1] * inv_lo);
        float2 v1 = make_float2(o[t][2] * inv_hi, o[t][3] * inv_hi);
        __half2 h0 = __floats2half2_rn(v0.x, v0.y);
        __half2 h1 = __floats2half2_rn(v1.x, v1.y);
        float2 f0 = __half22float2(h0);
        float2 f1 = __half22float2(h1);
        __half2 l0 = __floats2half2_rn(v0.x - f0.x, v0.y - f0.y);
        __half2 l1 = __floats2half2_rn(v1.x - f1.x, v1.y - f1.y);
        *(__half2*)(Ohi + rg * DDIM + cb2 + 8 * t)       = h0;
        *(__half2*)(Olo + rg * DDIM + cb2 + 8 * t)       = l0;
        *(__half2*)(Ohi + (rg + 8) * DDIM + cb2 + 8 * t) = h1;
        *(__half2*)(Olo + (rg + 8) * DDIM + cb2 + 8 * t) = l1;
    }
}

// ---------------------------------------------------------------------------
extern "C" void kernel_launch(void* const* d_in, const int* in_sizes, int n_in,
                              void* d_out, int out_size)
{
    (void)in_sizes; (void)n_in; (void)out_size;
    const float* query  = (const float*)d_in[0];
    const float* key_in = (const float*)d_in[1];
    const float* value  = (const float*)d_in[2];
    const float* Wq = (const float*)d_in[3];
    const float* bq = (const float*)d_in[4];
    const float* Wk = (const float*)d_in[5];
    const float* bk = (const float*)d_in[6];
    const float* Wv = (const float*)d_in[7];
    const float* bv = (const float*)d_in[8];
    const float* Wo = (const float*)d_in[9];
    const float* bo = (const float*)d_in[10];
    float* out = (float*)d_out;

    __half *pXin, *pW, *pQ, *pK, *pV, *pAh, *pAl;
    cudaGetSymbolAddress((void**)&pXin, g_Xin);
    cudaGetSymbolAddress((void**)&pW,   g_W16);
    cudaGetSymbolAddress((void**)&pQ,   g_Q);
    cudaGetSymbolAddress((void**)&pK,   g_K);
    cudaGetSymbolAddress((void**)&pV,   g_V);
    cudaGetSymbolAddress((void**)&pAh,  g_Ahi);
    cudaGetSymbolAddress((void**)&pAl,  g_Alo);

    cudaFuncSetAttribute(gemm_f16_k<true>,
                         cudaFuncAttributeMaxDynamicSharedMemorySize, GT_SMEM2P);
    cudaFuncSetAttribute(gemm_f16_k<false>,
                         cudaFuncAttributeMaxDynamicSharedMemorySize, GT_SMEM1P);
    cudaFuncSetAttribute(flash_mma_k,
                         cudaFuncAttributeMaxDynamicSharedMemorySize, FA_SMEM);

    const int nW4 = DDIM * DDIM / 4;
    const int nX4 = MROWS * DDIM / 4;
    const int gW = (nW4 + 255) / 256;
    const int gX = (nX4 + 255) / 256;
    __half* pWq = pW;
    __half* pWk = pW + (size_t)DDIM * DDIM;
    __half* pWv = pW + 2 * (size_t)DDIM * DDIM;
    __half* pWo = pW + 3 * (size_t)DDIM * DDIM;
    __half* pXq = pXin;
    __half* pXk = pXin + (size_t)MROWS * DDIM;
    __half* pXv = pXin + 2 * (size_t)MROWS * DDIM;

    cvt4_f32_k<<<dim3(gW, 4), 256>>>(Wq, Wk, Wv, Wo, pW, nW4);
    cvt3_f32_k<<<dim3(gX, 3), 256>>>(query, key_in, value, pXin, nX4);

    dim3 gg(DDIM / 128, MROWS / 128);

    gemm_f16_k<false><<<gg, 512, GT_SMEM1P>>>(pXq, nullptr, pWq, bq, nullptr, pQ, nullptr);
    gemm_f16_k<false><<<gg, 512, GT_SMEM1P>>>(pXk, nullptr, pWk, bk, nullptr, pK, nullptr);
    gemm_f16_k<false><<<gg, 512, GT_SMEM1P>>>(pXv, nullptr, pWv, bv, nullptr, pV, nullptr);

    flash_mma_k<<<dim3(SEQ / 128, NHEADS, BATCH), 256, FA_SMEM>>>(
        pQ, pK, pV, pAh, pAl);

    gemm_f16_k<true><<<gg, 512, GT_SMEM2P>>>(pAh, pAl, pWo, bo, out, nullptr, nullptr);
}

// round 13
// speedup vs baseline: 1.6399x; 1.1715x over previous
#include <cuda_runtime.h>
#include <cuda_fp16.h>
#include <math.h>
#include <stdint.h>

#define MROWS  4096   // B*S
#define DDIM   2048
#define NHEADS 16
#define HDIM   128
#define SEQ    2048
#define BATCH  2

// Scratch (static device globals; no runtime allocation)
__device__ __half g_Xin[3 * MROWS * DDIM]; // query/key/value in f16
__device__ __half g_W16[4 * DDIM * DDIM];  // Wq,Wk,Wv,Wo in f16
__device__ __half g_QKV[3 * MROWS * DDIM]; // projected Q,K,V (f16)
__device__ __half g_A[MROWS * DDIM];       // attention out (f16)

// ---- helpers ----------------------------------------------------------------
__device__ __forceinline__ uint32_t smem_u32(const void* p) {
    uint32_t a;
    asm("{ .reg .u64 t; cvta.to.shared.u64 t, %1; cvt.u32.u64 %0, t; }"
        : "=r"(a) : "l"(p));
    return a;
}
__device__ __forceinline__ uint32_t sw128(uint32_t off) {
    return off ^ ((off >> 3) & 0x70);
}
__device__ __forceinline__ void cp16(uint32_t sdst, const void* gsrc) {
    asm volatile("cp.async.cg.shared.global [%0], [%1], 16;"
                 :: "r"(sdst), "l"(gsrc));
}
#define CP_COMMIT() asm volatile("cp.async.commit_group;" ::: "memory")
#define CP_WAIT(n)  asm volatile("cp.async.wait_group %0;" :: "n"(n) : "memory")

__device__ __forceinline__ void ldmx4(uint32_t* r, uint32_t addr) {
    asm volatile("ldmatrix.sync.aligned.m8n8.x4.shared.b16 {%0,%1,%2,%3}, [%4];"
                 : "=r"(r[0]), "=r"(r[1]), "=r"(r[2]), "=r"(r[3]) : "r"(addr));
}
__device__ __forceinline__ void ldmx4t(uint32_t* r, uint32_t addr) {
    asm volatile("ldmatrix.sync.aligned.m8n8.x4.trans.shared.b16 {%0,%1,%2,%3}, [%4];"
                 : "=r"(r[0]), "=r"(r[1]), "=r"(r[2]), "=r"(r[3]) : "r"(addr));
}
__device__ __forceinline__ void mma_f16(float* c, const uint32_t* a,
                                        uint32_t b0, uint32_t b1) {
    asm volatile(
        "mma.sync.aligned.m16n8k16.row.col.f32.f16.f16.f32 "
        "{%0,%1,%2,%3}, {%4,%5,%6,%7}, {%8,%9}, {%0,%1,%2,%3};"
        : "+f"(c[0]), "+f"(c[1]), "+f"(c[2]), "+f"(c[3])
        : "r"(a[0]), "r"(a[1]), "r"(a[2]), "r"(a[3]), "r"(b0), "r"(b1));
}
__device__ __forceinline__ uint32_t exp2x2(float d0, float d1) {
    uint32_t p;
    asm("{ .reg .b32 t;\n\t"
        "cvt.rn.f16x2.f32 t, %1, %2;\n\t"
        "ex2.approx.f16x2 %0, t; }"
        : "=r"(p) : "f"(d1), "f"(d0));
    return p;
}
__device__ __forceinline__ float ex2f(float x) {
    float r;
    asm("ex2.approx.ftz.f32 %0, %1;" : "=f"(r) : "f"(x));
    return r;
}

// ---------------------------------------------------------------------------
// Prep kernels (memory-bound)
// ---------------------------------------------------------------------------
__global__ __launch_bounds__(256)
void cvt3_f32_k(const float* __restrict__ x0, const float* __restrict__ x1,
                const float* __restrict__ x2, __half* __restrict__ y, int n4)
{
    int i = blockIdx.x * 256 + threadIdx.x;
    if (i >= n4) return;
    const float* src = (blockIdx.y == 0) ? x0 : (blockIdx.y == 1) ? x1 : x2;
    float4 v = ((const float4*)src)[i];
    __half2 h01 = __floats2half2_rn(v.x, v.y);
    __half2 h23 = __floats2half2_rn(v.z, v.w);
    ((uint2*)(y + (size_t)blockIdx.y * MROWS * DDIM))[i] =
        make_uint2(*(uint32_t*)&h01, *(uint32_t*)&h23);
}
__global__ __launch_bounds__(256)
void cvt4_f32_k(const float* __restrict__ w0, const float* __restrict__ w1,
                const float* __restrict__ w2, const float* __restrict__ w3,
                __half* __restrict__ y, int n4)
{
    int i = blockIdx.x * 256 + threadIdx.x;
    if (i >= n4) return;
    const float* src = (blockIdx.y == 0) ? w0 : (blockIdx.y == 1) ? w1
                     : (blockIdx.y == 2) ? w2 : w3;
    float4 v = ((const float4*)src)[i];
    __half2 h01 = __floats2half2_rn(v.x, v.y);
    __half2 h23 = __floats2half2_rn(v.z, v.w);
    ((uint2*)(y + (size_t)blockIdx.y * DDIM * DDIM))[i] =
        make_uint2(*(uint32_t*)&h01, *(uint32_t*)&h23);
}

// ---------------------------------------------------------------------------
// GEMM core (NT, 1-pass f16, cp.async 2-stage): acc = A @ Bw^T
// CTA 128x128, BK=64, 512 threads (4x4 warps, 32x32 warp tile).
// ---------------------------------------------------------------------------
#define GT_TILE   (128 * 64 * 2)      // 16 KB
#define GT_STAGE  (2 * GT_TILE)       // 32 KB
#define GT_NCHUNK (DDIM / 64)         // 32
#define GT_SMEM   (2 * GT_STAGE + 1024)

__device__ __forceinline__ void gemm_core(
    const __half* __restrict__ A, const __half* __restrict__ Bw,
    uint32_t sb, int m0, int n0, int tid, float acc[2][4][4])
{
    const int lane = tid & 31;
    const int wid  = tid >> 5;
    const int wm = wid >> 2;
    const int wn = wid & 3;

    const int crow = tid >> 3;
    const int cch  = tid & 7;
    const uint32_t soff0 = sw128((uint32_t)(crow * 128 + cch * 16));
    const uint32_t soff1 = sw128((uint32_t)((crow + 64) * 128 + cch * 16));
    const __half* gA0 = A  + (size_t)(m0 + crow) * DDIM + cch * 8;
    const __half* gB0 = Bw + (size_t)(n0 + crow) * DDIM + cch * 8;
    const size_t rsk = (size_t)64 * DDIM;

    const int a_row = wm * 32 + (lane & 15);
    const int a_cb  = (lane >> 4) * 16;
    const int b_row = wn * 32 + (lane & 7) + ((lane >> 4) << 3);
    const int b_cb  = ((lane >> 3) & 1) * 16;

    {
        const uint32_t st = sb;
        cp16(st + soff0, gA0);           cp16(st + soff1, gA0 + rsk);
        cp16(st + GT_TILE + soff0, gB0); cp16(st + GT_TILE + soff1, gB0 + rsk);
        CP_COMMIT();
    }

    for (int chunk = 0; chunk < GT_NCHUNK; chunk++) {
        if (chunk + 1 < GT_NCHUNK) {
            const int kh = (chunk + 1) * 64;
            const uint32_t st = sb + ((chunk + 1) & 1) * GT_STAGE;
            cp16(st + soff0, gA0 + kh);           cp16(st + soff1, gA0 + kh + rsk);
            cp16(st + GT_TILE + soff0, gB0 + kh); cp16(st + GT_TILE + soff1, gB0 + kh + rsk);
            CP_COMMIT();
            CP_WAIT(1);
        } else {
            CP_WAIT(0);
        }
        __syncthreads();

        const uint32_t sA = sb + (chunk & 1) * GT_STAGE;
        const uint32_t sB = sA + GT_TILE;

#pragma unroll
        for (int ks = 0; ks < 4; ks++) {
            const uint32_t kb = ks * 32;
            uint32_t ah[2][4], bh[2][4];
#pragma unroll
            for (int mt = 0; mt < 2; mt++) {
                const uint32_t off =
                    sw128((uint32_t)((a_row + mt * 16) * 128) + kb + a_cb);
                ldmx4(ah[mt], sA + off);
            }
#pragma unroll
            for (int nt = 0; nt < 2; nt++) {
                const uint32_t off =
                    sw128((uint32_t)((b_row + nt * 16) * 128) + kb + b_cb);
                ldmx4(bh[nt], sB + off);
            }
#pragma unroll
            for (int mt = 0; mt < 2; mt++)
#pragma unroll
                for (int nt = 0; nt < 2; nt++)
#pragma unroll
                    for (int h = 0; h < 2; h++)
                        mma_f16(acc[mt][nt * 2 + h], ah[mt],
                                bh[nt][2 * h], bh[nt][2 * h + 1]);
        }
        __syncthreads();
    }
}

// fused QKV: grid.z selects which projection; f16 output
__global__ __launch_bounds__(512)
void gemm_qkv_k(const __half* __restrict__ Xin, const __half* __restrict__ W,
                const float* __restrict__ b0, const float* __restrict__ b1,
                const float* __restrict__ b2, __half* __restrict__ Yout)
{
    extern __shared__ char dsm[];
    char* smc = (char*)(((uintptr_t)dsm + 1023) & ~(uintptr_t)1023);
    const uint32_t sb = smem_u32(smc);

    const int z = blockIdx.z;
    const __half* A  = Xin + (size_t)z * MROWS * DDIM;
    const __half* Bw = W   + (size_t)z * DDIM * DDIM;
    const float* bias = (z == 0) ? b0 : (z == 1) ? b1 : b2;
    __half* Y = Yout + (size_t)z * MROWS * DDIM;

    const int tid = threadIdx.x;
    const int m0 = blockIdx.y * 128;
    const int n0 = blockIdx.x * 128;

    float acc[2][4][4];
#pragma unroll
    for (int i = 0; i < 2; i++)
#pragma unroll
        for (int j = 0; j < 4; j++)
#pragma unroll
            for (int q = 0; q < 4; q++) acc[i][j][q] = 0.f;

    gemm_core(A, Bw, sb, m0, n0, tid, acc);

    const int lane = tid & 31;
    const int wid  = tid >> 5;
    const int wm = wid >> 2, wn = wid & 3;
    const int g  = lane >> 2, tg = lane & 3;
#pragma unroll
    for (int mt = 0; mt < 2; mt++) {
        const int row = m0 + wm * 32 + mt * 16 + g;
#pragma unroll
        for (int nt8 = 0; nt8 < 4; nt8++) {
            const int col = n0 + wn * 32 + nt8 * 8 + tg * 2;
            const float bb0 = bias[col], bb1 = bias[col + 1];
            *(__half2*)(Y + (size_t)row * DDIM + col) =
                __floats2half2_rn(acc[mt][nt8][0] + bb0, acc[mt][nt8][1] + bb1);
            *(__half2*)(Y + (size_t)(row + 8) * DDIM + col) =
                __floats2half2_rn(acc[mt][nt8][2] + bb0, acc[mt][nt8][3] + bb1);
        }
    }
}

// O projection: fp32 output
__global__ __launch_bounds__(512)
void gemm_o_k(const __half* __restrict__ A, const __half* __restrict__ Bw,
              const float* __restrict__ bias, float* __restrict__ Y)
{
    extern __shared__ char dsm[];
    char* smc = (char*)(((uintptr_t)dsm + 1023) & ~(uintptr_t)1023);
    const uint32_t sb = smem_u32(smc);

    const int tid = threadIdx.x;
    const int m0 = blockIdx.y * 128;
    const int n0 = blockIdx.x * 128;

    float acc[2][4][4];
#pragma unroll
    for (int i = 0; i < 2; i++)
#pragma unroll
        for (int j = 0; j < 4; j++)
#pragma unroll
            for (int q = 0; q < 4; q++) acc[i][j][q] = 0.f;

    gemm_core(A, Bw, sb, m0, n0, tid, acc);

    const int lane = tid & 31;
    const int wid  = tid >> 5;
    const int wm = wid >> 2, wn = wid & 3;
    const int g  = lane >> 2, tg = lane & 3;
#pragma unroll
    for (int mt = 0; mt < 2; mt++) {
        const int row = m0 + wm * 32 + mt * 16 + g;
#pragma unroll
        for (int nt8 = 0; nt8 < 4; nt8++) {
            const int col = n0 + wn * 32 + nt8 * 8 + tg * 2;
            const float bb0 = bias[col], bb1 = bias[col + 1];
            float* y0 = Y + (size_t)row * DDIM + col;
            float* y1 = Y + (size_t)(row + 8) * DDIM + col;
            y0[0] = acc[mt][nt8][0] + bb0; y0[1] = acc[mt][nt8][1] + bb1;
            y1[0] = acc[mt][nt8][2] + bb0; y1[1] = acc[mt][nt8][3] + bb1;
        }
    }
}

// ---------------------------------------------------------------------------
// Flash attention, tensor-core, cp.async double-buffered K/V.
// Q/K/V single f16 (1-pass QK, 1-pass AV). Output single f16.
// BM=128/CTA, 8 warps x 16 rows, BN=128, Hd=128. smem 160KB.
// ---------------------------------------------------------------------------
#define FKS 0.12751744f   // (1/sqrt(128)) * log2(e)
#define FA_SMEM (5 * 32768)

__device__ __forceinline__ uint32_t off16(uint32_t row, uint32_t cb) {
    return ((cb >> 7) << 14) + sw128((row << 7) + (cb & 127));
}

__global__ __launch_bounds__(256)
void flash_mma_k(const __half* __restrict__ Qp,
                 const __half* __restrict__ Kp, const __half* __restrict__ Vp,
                 __half* __restrict__ O)
{
    extern __shared__ char fsm[];
    char* cQ = fsm;
    const uint32_t sQ = smem_u32(fsm);
    const uint32_t sStage0 = sQ + 32768;      // [K0|V0], [K1|V1] each 64KB

    const int tid  = threadIdx.x;
    const int wid  = tid >> 5;
    const int lane = tid & 31;
    const int qt = blockIdx.x, h = blockIdx.y, b = blockIdx.z;
    const int wr = wid << 4;
    const int hc = h * HDIM;
    const size_t rowbase = (size_t)b * SEQ;

    for (int i = tid; i < 2048; i += 256) {
        const uint32_t row = i >> 4;
        const uint32_t cb  = (i & 15) * 16;
        const size_t g = (rowbase + qt * 128 + row) * DDIM + hc + (cb >> 1);
        *(uint4*)(cQ + off16(row, cb)) = *(const uint4*)(Qp + g);
    }

    const uint32_t lrow = tid >> 4;
    const uint32_t lcb  = (tid & 15) * 16;
    const uint32_t loff[8] = {
        off16(lrow, lcb),       off16(lrow + 16, lcb),
        off16(lrow + 32, lcb),  off16(lrow + 48, lcb),
        off16(lrow + 64, lcb),  off16(lrow + 80, lcb),
        off16(lrow + 96, lcb),  off16(lrow + 112, lcb)
    };

    {
        const uint32_t st = sStage0;
#pragma unroll
        for (int t = 0; t < 8; t++) {
            const size_t g = (rowbase + lrow + 16 * t) * DDIM + hc + (lcb >> 1);
            cp16(st + loff[t], Kp + g);
            cp16(st + 32768 + loff[t], Vp + g);
        }
        CP_COMMIT();
    }

    float o[17][4];
#pragma unroll
    for (int t = 0; t < 17; t++)
#pragma unroll
        for (int q = 0; q < 4; q++) o[t][q] = 0.f;
    float m_lo = -1e30f, m_hi = -1e30f;

    const uint32_t b_ones = (lane < 4) ? 0x3C003C00u : 0u;

    for (int jt = 0; jt < SEQ / 128; jt++) {
        if (jt + 1 < SEQ / 128) {
            const uint32_t st = sStage0 + ((jt + 1) & 1) * 65536;
#pragma unroll
            for (int t = 0; t < 8; t++) {
                const size_t g = (rowbase + (jt + 1) * 128 + lrow + 16 * t) * DDIM
                               + hc + (lcb >> 1);
                cp16(st + loff[t], Kp + g);
                cp16(st + 32768 + loff[t], Vp + g);
            }
            CP_COMMIT();
            CP_WAIT(1);
        } else {
            CP_WAIT(0);
        }
        __syncthreads();

        const uint32_t sK = sStage0 + (jt & 1) * 65536;
        const uint32_t sV = sK + 32768;

        float s[16][4];
#pragma unroll
        for (int t = 0; t < 16; t++)
#pragma unroll
            for (int q = 0; q < 4; q++) s[t][q] = 0.f;

#pragma unroll
        for (int ks = 0; ks < 8; ks++) {
            const uint32_t kb = ks * 32;
            uint32_t ah[4];
            const uint32_t aoff = off16(wr + (lane & 15), kb + ((lane >> 4) << 4));
            ldmx4(ah, sQ + aoff);
#pragma unroll
            for (int ntp = 0; ntp < 8; ntp++) {
                uint32_t bh[4];
                const uint32_t nr  = ntp * 16 + (lane & 7) + ((lane >> 4) << 3);
                const uint32_t boff = off16(nr, kb + (((lane >> 3) & 1) << 4));
                ldmx4(bh, sK + boff);
#pragma unroll
                for (int hh = 0; hh < 2; hh++)
                    mma_f16(s[ntp * 2 + hh], ah, bh[2 * hh], bh[2 * hh + 1]);
            }
        }

        float mloc_lo = -1e30f, mloc_hi = -1e30f;
#pragma unroll
        for (int t = 0; t < 16; t++) {
            mloc_lo = fmaxf(mloc_lo, fmaxf(s[t][0], s[t][1]));
            mloc_hi = fmaxf(mloc_hi, fmaxf(s[t][2], s[t][3]));
        }
        mloc_lo = fmaxf(mloc_lo, __shfl_xor_sync(0xffffffffu, mloc_lo, 1));
        mloc_lo = fmaxf(mloc_lo, __shfl_xor_sync(0xffffffffu, mloc_lo, 2));
        mloc_hi = fmaxf(mloc_hi, __shfl_xor_sync(0xffffffffu, mloc_hi, 1));
        mloc_hi = fmaxf(mloc_hi, __shfl_xor_sync(0xffffffffu, mloc_hi, 2));

        const float mn_lo = fmaxf(m_lo, mloc_lo);
        const float mn_hi = fmaxf(m_hi, mloc_hi);
        const float al_lo = ex2f((m_lo - mn_lo) * FKS);
        const float al_hi = ex2f((m_hi - mn_hi) * FKS);
        m_lo = mn_lo; m_hi = mn_hi;
        const float mk_lo = mn_lo * FKS;
        const float mk_hi = mn_hi * FKS;

        uint32_t pex[16][2];
#pragma unroll
        for (int t = 0; t < 16; t++) {
            pex[t][0] = exp2x2(fmaf(s[t][0], FKS, -mk_lo), fmaf(s[t][1], FKS, -mk_lo));
            pex[t][1] = exp2x2(fmaf(s[t][2], FKS, -mk_hi), fmaf(s[t][3], FKS, -mk_hi));
        }
#pragma unroll
        for (int t = 0; t < 17; t++) {
            o[t][0] *= al_lo; o[t][1] *= al_lo;
            o[t][2] *= al_hi; o[t][3] *= al_hi;
        }

#pragma unroll
        for (int ks = 0; ks < 8; ks++) {
            uint32_t a[4] = { pex[2 * ks][0], pex[2 * ks][1],
                              pex[2 * ks + 1][0], pex[2 * ks + 1][1] };
            const uint32_t vr = ks * 16 + (lane & 15);
#pragma unroll
            for (int dp = 0; dp < 8; dp++) {
                uint32_t vh[4];
                const uint32_t voff = off16(vr, dp * 32 + ((lane >> 4) << 4));
                ldmx4t(vh, sV + voff);
                mma_f16(o[2 * dp],     a, vh[0], vh[1]);
                mma_f16(o[2 * dp + 1], a, vh[2], vh[3]);
            }
            mma_f16(o[16], a, b_ones, b_ones);
        }
        __syncthreads();
    }

    // epilogue: divide by l, store single f16
    const float l_lo = __shfl_sync(0xffffffffu, o[16][0], lane & 28);
    const float l_hi = __shfl_sync(0xffffffffu, o[16][2], lane & 28);
    const float inv_lo = 1.f / l_lo;
    const float inv_hi = 1.f / l_hi;
    const size_t rg = rowbase + qt * 128 + wr + (lane >> 2);
    const int cb2 = hc + 2 * (lane & 3);
#pragma unroll
    for (int t = 0; t < 16; t++) {
        *(__half2*)(O + rg * DDIM + cb2 + 8 * t) =
            __floats2half2_rn(o[t][0] * inv_lo, o[t][1] * inv_lo);
        *(__half2*)(O + (rg + 8) * DDIM + cb2 + 8 * t) =
            __floats2half2_rn(o[t][2] * inv_hi, o[t][3] * inv_hi);
    }
}

// ---------------------------------------------------------------------------
extern "C" void kernel_launch(void* const* d_in, const int* in_sizes, int n_in,
                              void* d_out, int out_size)
{
    (void)in_sizes; (void)n_in; (void)out_size;
    const float* query  = (const float*)d_in[0];
    const float* key_in = (const float*)d_in[1];
    const float* value  = (const float*)d_in[2];
    const float* Wq = (const float*)d_in[3];
    const float* bq = (const float*)d_in[4];
    const float* Wk = (const float*)d_in[5];
    const float* bk = (const float*)d_in[6];
    const float* Wv = (const float*)d_in[7];
    const float* bv = (const float*)d_in[8];
    const float* Wo = (const float*)d_in[9];
    const float* bo = (const float*)d_in[10];
    float* out = (float*)d_out;

    __half *pXin, *pW, *pQKV, *pA;
    cudaGetSymbolAddress((void**)&pXin, g_Xin);
    cudaGetSymbolAddress((void**)&pW,   g_W16);
    cudaGetSymbolAddress((void**)&pQKV, g_QKV);
    cudaGetSymbolAddress((void**)&pA,   g_A);

    cudaFuncSetAttribute(gemm_qkv_k,
                         cudaFuncAttributeMaxDynamicSharedMemorySize, GT_SMEM);
    cudaFuncSetAttribute(gemm_o_k,
                         cudaFuncAttributeMaxDynamicSharedMemorySize, GT_SMEM);
    cudaFuncSetAttribute(flash_mma_k,
                         cudaFuncAttributeMaxDynamicSharedMemorySize, FA_SMEM);

    const int nW4 = DDIM * DDIM / 4;
    const int nX4 = MROWS * DDIM / 4;
    const int gW = (nW4 + 255) / 256;
    const int gX = (nX4 + 255) / 256;
    __half* pWo16 = pW + 3 * (size_t)DDIM * DDIM;
    __half* pQ = pQKV;
    __half* pK = pQKV + (size_t)MROWS * DDIM;
    __half* pV = pQKV + 2 * (size_t)MROWS * DDIM;

    cvt4_f32_k<<<dim3(gW, 4), 256>>>(Wq, Wk, Wv, Wo, pW, nW4);
    cvt3_f32_k<<<dim3(gX, 3), 256>>>(query, key_in, value, pXin, nX4);

    gemm_qkv_k<<<dim3(DDIM / 128, MROWS / 128, 3), 512, GT_SMEM>>>(
        pXin, pW, bq, bk, bv, pQKV);

    flash_mma_k<<<dim3(SEQ / 128, NHEADS, BATCH), 256, FA_SMEM>>>(
        pQ, pK, pV, pA);

    gemm_o_k<<<dim3(DDIM / 128, MROWS / 128), 512, GT_SMEM>>>(pA, pWo16, bo, out);
}